// round 2
// baseline (speedup 1.0000x reference)
#include <cuda_runtime.h>
#include <cuda_bf16.h>

// LIF spike scan: x [B=32, T=16, C=128, H=32, W=32] fp32 -> spikes (fp32, same shape).
// Per site: mem = mem*TAU + x_t; s = (mem >= THRESH); mem = (1-s)*mem.
//
// HBM-bound (512 MiB total). R2 strategy:
//  - 8 floats per thread (two contiguous float4 => 1024B per warp per step)
//  - explicitly batch 8 timesteps of loads before compute/store (high MLP,
//    coarse read/write phasing to reduce DRAM bus turnaround)
//  - __ldcs/__stcs streaming hints: nothing is reused, keep L2 evict-first.

#define LIF_T      16
#define LIF_THRESH 0.5f
#define LIF_TAU    0.25f
#define LIF_GROUP  8            // timesteps per load/compute/store group

__global__ __launch_bounds__(256) void lif_spike_kernel(
    const float4* __restrict__ x,   // [B, T, CHW/4] as float4
    float4* __restrict__ out,
    int chw4)                        // C*H*W/4 = 32768
{
    // Each thread owns 8 consecutive floats = 2 consecutive float4.
    int gid  = blockIdx.x * blockDim.x + threadIdx.x;   // [0, B * chw/8)
    int chw8 = chw4 >> 1;
    int b  = gid / chw8;
    int sp = gid - b * chw8;

    // float4 offset of (b, t=0, this thread's pair)
    long base = (long)b * (LIF_T * (long)chw4) + (long)sp * 2;

    float4 mem0 = make_float4(0.f, 0.f, 0.f, 0.f);
    float4 mem1 = make_float4(0.f, 0.f, 0.f, 0.f);

#pragma unroll
    for (int g = 0; g < LIF_T / LIF_GROUP; g++) {
        float4 v0[LIF_GROUP], v1[LIF_GROUP];

        // Front-batch all loads of this group (independent -> high MLP)
#pragma unroll
        for (int t = 0; t < LIF_GROUP; t++) {
            long off = base + (long)(g * LIF_GROUP + t) * chw4;
            v0[t] = __ldcs(&x[off]);
            v1[t] = __ldcs(&x[off + 1]);
        }

        // Sequential LIF scan in registers (8 lanes)
#pragma unroll
        for (int t = 0; t < LIF_GROUP; t++) {
            mem0.x = fmaf(mem0.x, LIF_TAU, v0[t].x);
            mem0.y = fmaf(mem0.y, LIF_TAU, v0[t].y);
            mem0.z = fmaf(mem0.z, LIF_TAU, v0[t].z);
            mem0.w = fmaf(mem0.w, LIF_TAU, v0[t].w);
            mem1.x = fmaf(mem1.x, LIF_TAU, v1[t].x);
            mem1.y = fmaf(mem1.y, LIF_TAU, v1[t].y);
            mem1.z = fmaf(mem1.z, LIF_TAU, v1[t].z);
            mem1.w = fmaf(mem1.w, LIF_TAU, v1[t].w);

            float s0x = (mem0.x >= LIF_THRESH) ? 1.f : 0.f;
            float s0y = (mem0.y >= LIF_THRESH) ? 1.f : 0.f;
            float s0z = (mem0.z >= LIF_THRESH) ? 1.f : 0.f;
            float s0w = (mem0.w >= LIF_THRESH) ? 1.f : 0.f;
            float s1x = (mem1.x >= LIF_THRESH) ? 1.f : 0.f;
            float s1y = (mem1.y >= LIF_THRESH) ? 1.f : 0.f;
            float s1z = (mem1.z >= LIF_THRESH) ? 1.f : 0.f;
            float s1w = (mem1.w >= LIF_THRESH) ? 1.f : 0.f;

            mem0.x = (s0x != 0.f) ? 0.f : mem0.x;
            mem0.y = (s0y != 0.f) ? 0.f : mem0.y;
            mem0.z = (s0z != 0.f) ? 0.f : mem0.z;
            mem0.w = (s0w != 0.f) ? 0.f : mem0.w;
            mem1.x = (s1x != 0.f) ? 0.f : mem1.x;
            mem1.y = (s1y != 0.f) ? 0.f : mem1.y;
            mem1.z = (s1z != 0.f) ? 0.f : mem1.z;
            mem1.w = (s1w != 0.f) ? 0.f : mem1.w;

            v0[t] = make_float4(s0x, s0y, s0z, s0w);
            v1[t] = make_float4(s1x, s1y, s1z, s1w);
        }

        // Batch the group's stores (streaming, evict-first)
#pragma unroll
        for (int t = 0; t < LIF_GROUP; t++) {
            long off = base + (long)(g * LIF_GROUP + t) * chw4;
            __stcs(&out[off],     v0[t]);
            __stcs(&out[off + 1], v1[t]);
        }
    }
}

extern "C" void kernel_launch(void* const* d_in, const int* in_sizes, int n_in,
                              void* d_out, int out_size)
{
    const float* x = (const float*)d_in[0];
    float* out = (float*)d_out;

    // x: [32, 16, 128, 32, 32] => B=32, T=16, CHW=131072
    const int chw  = 128 * 32 * 32;                 // 131072
    const int chw4 = chw / 4;                       // 32768
    const int B    = in_sizes[0] / (LIF_T * chw);   // 32
    const int n_threads_total = B * (chw / 8);      // 524288

    const int threads = 256;
    const int blocks = n_threads_total / threads;   // 2048

    lif_spike_kernel<<<blocks, threads>>>(
        (const float4*)x, (float4*)out, chw4);
}

// round 3
// speedup vs baseline: 1.0444x; 1.0444x over previous
#include <cuda_runtime.h>
#include <cuda_bf16.h>

// LIF spike scan: x [B=32, T=16, C=128, H=32, W=32] fp32 -> spikes (fp32, same shape).
// Per site: mem = mem*TAU + x_t; s = (mem >= THRESH); mem = (1-s)*mem.
//
// HBM-bound (512 MiB total traffic). R3 = R1 structure (one float4 per thread,
// 32 regs, ~87% occupancy — occupancy is the latency hider, per R2 post-mortem)
// + streaming cache hints (__ldcs/__stcs): zero reuse, keep L2 evict-first.

#define LIF_T      16
#define LIF_THRESH 0.5f
#define LIF_TAU    0.25f

__global__ __launch_bounds__(256) void lif_spike_kernel(
    const float4* __restrict__ x,   // [B, T, CHW/4] viewed as float4
    float4* __restrict__ out,
    int chw4,                        // C*H*W/4 = 32768
    int n_sites)                     // B * chw4
{
    int gid = blockIdx.x * blockDim.x + threadIdx.x;
    if (gid >= n_sites) return;

    int b  = gid / chw4;
    int sp = gid - b * chw4;

    // element offset of (b, t=0, sp) in float4 units
    long base = (long)b * (LIF_T * (long)chw4) + sp;

    // All 16 time-step loads are independent; ptxas schedules/interleaves.
    float4 v[LIF_T];
#pragma unroll
    for (int t = 0; t < LIF_T; t++) {
        v[t] = __ldcs(&x[base + (long)t * chw4]);
    }

    // Sequential LIF scan in registers, 4 lanes in parallel
    float4 mem = make_float4(0.f, 0.f, 0.f, 0.f);
#pragma unroll
    for (int t = 0; t < LIF_T; t++) {
        mem.x = fmaf(mem.x, LIF_TAU, v[t].x);
        mem.y = fmaf(mem.y, LIF_TAU, v[t].y);
        mem.z = fmaf(mem.z, LIF_TAU, v[t].z);
        mem.w = fmaf(mem.w, LIF_TAU, v[t].w);

        float sx = (mem.x >= LIF_THRESH) ? 1.f : 0.f;
        float sy = (mem.y >= LIF_THRESH) ? 1.f : 0.f;
        float sz = (mem.z >= LIF_THRESH) ? 1.f : 0.f;
        float sw = (mem.w >= LIF_THRESH) ? 1.f : 0.f;

        // hard reset
        mem.x = (sx != 0.f) ? 0.f : mem.x;
        mem.y = (sy != 0.f) ? 0.f : mem.y;
        mem.z = (sz != 0.f) ? 0.f : mem.z;
        mem.w = (sw != 0.f) ? 0.f : mem.w;

        v[t] = make_float4(sx, sy, sz, sw);  // reuse v[] as output buffer
    }

#pragma unroll
    for (int t = 0; t < LIF_T; t++) {
        __stcs(&out[base + (long)t * chw4], v[t]);
    }
}

extern "C" void kernel_launch(void* const* d_in, const int* in_sizes, int n_in,
                              void* d_out, int out_size)
{
    const float* x = (const float*)d_in[0];
    float* out = (float*)d_out;

    // x: [32, 16, 128, 32, 32] => B=32, T=16, CHW=131072
    const int chw  = 128 * 32 * 32;                 // 131072
    const int chw4 = chw / 4;                       // 32768
    const int B    = in_sizes[0] / (LIF_T * chw);   // 32
    const int n_sites = B * chw4;                   // 1,048,576

    const int threads = 256;
    const int blocks = (n_sites + threads - 1) / threads;

    lif_spike_kernel<<<blocks, threads>>>(
        (const float4*)x, (float4*)out, chw4, n_sites);
}